// round 1
// baseline (speedup 1.0000x reference)
#include <cuda_runtime.h>
#include <math.h>

#define NN    2000
#define NPAD  2048
#define DD    128
#define HH    256
#define BPAIR 100000
#define KNEG  5
#define EPOS  200000
#define ENEG  200000
#define NSRC  1000

// ---------------- scratch (static device globals; no allocation) ----------------
__device__ float  g_adjP[NPAD * NPAD];   // padded adj
__device__ float  g_A2[NPAD * NPAD];     // adj @ adj
__device__ float  g_P[NPAD * NPAD];      // A2 @ adj, then gamma (normalized) in place
__device__ float  g_d[NPAD];             // diag(A2)
__device__ float  g_W1P[NPAD * HH];      // padded W1
__device__ float  g_T[NPAD * HH];        // gamma @ W1 -> tanh
__device__ float  g_h[NN * HH];          // concat(node_embed, sw_h)
__device__ double g_loss;

// ---------------- helpers ----------------
__global__ void k_zero_loss() { g_loss = 0.0; }

__global__ void k_pad_adj(const float* __restrict__ adj) {
    int idx = blockIdx.x * blockDim.x + threadIdx.x;
    if (idx >= NPAD * NPAD) return;
    int i = idx / NPAD, j = idx - i * NPAD;
    g_adjP[idx] = (i < NN && j < NN) ? adj[i * NN + j] : 0.f;
}

__global__ void k_pad_w1(const float* __restrict__ W1) {
    int idx = blockIdx.x * blockDim.x + threadIdx.x;
    if (idx >= NPAD * HH) return;
    int i = idx / HH;
    g_W1P[idx] = (i < NN) ? W1[idx] : 0.f;   // same stride HH, extra rows padded
}

__global__ void k_diag() {
    int i = blockIdx.x * blockDim.x + threadIdx.x;
    if (i < NPAD) g_d[i] = g_A2[i * NPAD + i];
}

// ---------------- SGEMM: C = A*B, row-major, M,N multiples of 128, K multiple of 8 ----------------
__global__ __launch_bounds__(256) void k_sgemm(const float* __restrict__ A,
                                               const float* __restrict__ B,
                                               float* __restrict__ C,
                                               int M, int N, int K) {
    const int BM = 128, BN = 128, BK = 8, TM = 8, TN = 8;
    __shared__ float As[BK][BM];   // transposed A tile
    __shared__ float Bs[BK][BN];

    int tid  = threadIdx.x;                 // 0..255
    int brow = blockIdx.y, bcol = blockIdx.x;
    int tcol = tid & 15;                    // 0..15
    int trow = tid >> 4;                    // 0..15

    int aRow = tid >> 1;                    // 0..127
    int aCol = (tid & 1) * 4;               // 0 or 4
    int bRow = tid >> 5;                    // 0..7
    int bCol = (tid & 31) * 4;              // 0..124

    const float* Ab = A + (size_t)brow * BM * K;
    const float* Bb = B + (size_t)bcol * BN;

    float acc[TM][TN];
#pragma unroll
    for (int i = 0; i < TM; i++)
#pragma unroll
        for (int j = 0; j < TN; j++) acc[i][j] = 0.f;

    for (int k0 = 0; k0 < K; k0 += BK) {
        float4 av = *(const float4*)(Ab + (size_t)aRow * K + k0 + aCol);
        As[aCol + 0][aRow] = av.x;
        As[aCol + 1][aRow] = av.y;
        As[aCol + 2][aRow] = av.z;
        As[aCol + 3][aRow] = av.w;
        float4 bv = *(const float4*)(Bb + (size_t)(k0 + bRow) * N + bCol);
        *(float4*)&Bs[bRow][bCol] = bv;
        __syncthreads();
#pragma unroll
        for (int k = 0; k < BK; k++) {
            float ra[TM], rb[TN];
#pragma unroll
            for (int i = 0; i < TM; i++) ra[i] = As[k][trow * TM + i];
#pragma unroll
            for (int j = 0; j < TN; j++) rb[j] = Bs[k][tcol * TN + j];
#pragma unroll
            for (int i = 0; i < TM; i++)
#pragma unroll
                for (int j = 0; j < TN; j++) acc[i][j] += ra[i] * rb[j];
        }
        __syncthreads();
    }

    float* Cb = C + (size_t)brow * BM * N + (size_t)bcol * BN;
#pragma unroll
    for (int i = 0; i < TM; i++) {
#pragma unroll
        for (int j = 0; j < TN; j += 4) {
            float4 v = make_float4(acc[i][j], acc[i][j + 1], acc[i][j + 2], acc[i][j + 3]);
            *(float4*)(Cb + (size_t)(trow * TM + i) * N + tcol * TN + j) = v;
        }
    }
}

// ---------------- gamma: P <- normalize_rows( where(d_i*d_j>0, P*adj/(d_i*d_j), 0) ) ----------------
__global__ __launch_bounds__(256) void k_gamma() {
    int r = blockIdx.x;                 // 0..NPAD-1
    int tid = threadIdx.x;              // 256 threads
    float dr = g_d[r];
    float sumsq = 0.f;
    for (int j = tid; j < NPAD; j += 256) {
        float a  = g_adjP[r * NPAD + j];
        float dj = g_d[j];
        float den = dr * dj;
        float g = 0.f;
        if (den > 0.f) g = (g_P[r * NPAD + j] * a) / den;
        g_P[r * NPAD + j] = g;
        sumsq += g * g;
    }
    __shared__ float red[256];
    red[tid] = sumsq;
    __syncthreads();
    for (int s = 128; s > 0; s >>= 1) {
        if (tid < s) red[tid] += red[tid + s];
        __syncthreads();
    }
    float inv = 1.f / fmaxf(sqrtf(red[0]), 1e-12f);
    for (int j = tid; j < NPAD; j += 256) {
        g_P[r * NPAD + j] *= inv;
    }
}

// ---------------- T <- tanh(T + b1) over first NN rows ----------------
__global__ void k_tanh_bias(const float* __restrict__ b1) {
    int idx = blockIdx.x * blockDim.x + threadIdx.x;
    if (idx >= NN * HH) return;
    g_T[idx] = tanhf(g_T[idx] + b1[idx & (HH - 1)]);
}

// ---------------- h[r] = [node_embed[r], T[r] @ W2 + b2] ----------------
__global__ __launch_bounds__(128) void k_fc2_concat(const float* __restrict__ W2,
                                                    const float* __restrict__ b2,
                                                    const float* __restrict__ node_embed) {
    int r = blockIdx.x;          // 0..NN-1
    int j = threadIdx.x;         // 0..127
    __shared__ float tr[HH];
    tr[j]       = g_T[r * HH + j];
    tr[j + 128] = g_T[r * HH + j + 128];
    __syncthreads();
    float s = b2[j];
#pragma unroll 8
    for (int k = 0; k < HH; k++) s += tr[k] * W2[k * DD + j];
    g_h[r * HH + DD + j] = s;
    g_h[r * HH + j]      = node_embed[r * DD + j];
}

// ---------------- skipgram loss ----------------
__device__ __forceinline__ float warp_sum(float v) {
#pragma unroll
    for (int off = 16; off; off >>= 1) v += __shfl_xor_sync(0xffffffffu, v, off);
    return v;
}

__global__ __launch_bounds__(256) void k_skipgram(const float* __restrict__ node_embed,
                                                  const float* __restrict__ context_embed,
                                                  const int* __restrict__ pos_u,
                                                  const int* __restrict__ pos_v,
                                                  const int* __restrict__ neg_v) {
    int gwarp = (blockIdx.x * blockDim.x + threadIdx.x) >> 5;
    int lane  = threadIdx.x & 31;
    int wib   = threadIdx.x >> 5;
    float loss = 0.f;
    if (gwarp < BPAIR) {
        int u = pos_u[gwarp];
        int v = pos_v[gwarp];
        float4 eu = ((const float4*)(node_embed    + (size_t)u * DD))[lane];
        float4 ev = ((const float4*)(context_embed + (size_t)v * DD))[lane];
        float pd = eu.x * ev.x + eu.y * ev.y + eu.z * ev.z + eu.w * ev.w;
        pd = warp_sum(pd);
        float pos = fminf(fmaxf(pd, -10.f), 10.f);
        loss = log1pf(expf(-pos));
#pragma unroll
        for (int k = 0; k < KNEG; k++) {
            int nv = neg_v[gwarp * KNEG + k];
            float4 en = ((const float4*)(context_embed + (size_t)nv * DD))[lane];
            float nd = en.x * eu.x + en.y * eu.y + en.z * eu.z + en.w * eu.w;
            nd = warp_sum(nd);
            float neg = fminf(fmaxf(nd, -10.f), 10.f);
            loss += log1pf(expf(neg));
        }
    }
    __shared__ float wl[8];
    if (lane == 0) wl[wib] = loss;
    __syncthreads();
    if (threadIdx.x == 0) {
        float s = 0.f;
#pragma unroll
        for (int w = 0; w < 8; w++) s += wl[w];
        atomicAdd(&g_loss, (double)s);
    }
}

__global__ void k_finalize(float* __restrict__ out) {
    out[0] = (float)(g_loss / (double)BPAIR);
}

// ---------------- edge scores: out[e] = dot(h[src[e]], h[off + dst[e]]) ----------------
__global__ __launch_bounds__(256) void k_score(const int* __restrict__ src,
                                               const int* __restrict__ dst,
                                               float* __restrict__ out, int E, int dstOff) {
    int gwarp = (blockIdx.x * blockDim.x + threadIdx.x) >> 5;
    int lane  = threadIdx.x & 31;
    if (gwarp >= E) return;
    const float4* a = (const float4*)(g_h + (size_t)src[gwarp] * HH);
    const float4* b = (const float4*)(g_h + (size_t)(dstOff + dst[gwarp]) * HH);
    float s = 0.f;
#pragma unroll
    for (int i = 0; i < 2; i++) {
        float4 x = a[lane + 32 * i];
        float4 y = b[lane + 32 * i];
        s += x.x * y.x + x.y * y.y + x.z * y.z + x.w * y.w;
    }
    s = warp_sum(s);
    if (lane == 0) out[gwarp] = s;
}

// ---------------- launch ----------------
extern "C" void kernel_launch(void* const* d_in, const int* in_sizes, int n_in,
                              void* d_out, int out_size) {
    const float* node_embed    = (const float*)d_in[0];
    const float* context_embed = (const float*)d_in[1];
    const float* adj           = (const float*)d_in[2];
    const float* W1            = (const float*)d_in[3];
    const float* b1            = (const float*)d_in[4];
    const float* W2            = (const float*)d_in[5];
    const float* b2            = (const float*)d_in[6];
    const int*   pos_u         = (const int*)d_in[7];
    const int*   pos_v         = (const int*)d_in[8];
    const int*   neg_v         = (const int*)d_in[9];
    const int*   pos_src       = (const int*)d_in[10];
    const int*   pos_dst       = (const int*)d_in[11];
    const int*   neg_src       = (const int*)d_in[12];
    const int*   neg_dst       = (const int*)d_in[13];
    float* out = (float*)d_out;

    float *adjP, *A2, *P;
    cudaGetSymbolAddress((void**)&adjP, g_adjP);
    cudaGetSymbolAddress((void**)&A2,   g_A2);
    cudaGetSymbolAddress((void**)&P,    g_P);
    float *W1P, *T;
    cudaGetSymbolAddress((void**)&W1P, g_W1P);
    cudaGetSymbolAddress((void**)&T,   g_T);

    // prep
    k_zero_loss<<<1, 1>>>();
    k_pad_adj<<<(NPAD * NPAD + 255) / 256, 256>>>(adj);
    k_pad_w1<<<(NPAD * HH + 255) / 256, 256>>>(W1);

    // skipgram loss (independent of graph pipeline)
    k_skipgram<<<(BPAIR * 32) / 256, 256>>>(node_embed, context_embed, pos_u, pos_v, neg_v);
    k_finalize<<<1, 1>>>(out);

    // A2 = adjP @ adjP ; P = A2 @ adjP
    dim3 gBig(NPAD / 128, NPAD / 128);
    k_sgemm<<<gBig, 256>>>(adjP, adjP, A2, NPAD, NPAD, NPAD);
    k_diag<<<(NPAD + 255) / 256, 256>>>();
    k_sgemm<<<gBig, 256>>>(A2, adjP, P, NPAD, NPAD, NPAD);

    // gamma (in place in P) with row normalization
    k_gamma<<<NPAD, 256>>>();

    // T = gamma @ W1P ; tanh(+b1) ; fc2 + concat
    dim3 gW1(HH / 128, NPAD / 128);
    k_sgemm<<<gW1, 256>>>(P, W1P, T, NPAD, HH, NPAD);
    k_tanh_bias<<<(NN * HH + 255) / 256, 256>>>(b1);
    k_fc2_concat<<<NN, 128>>>(W2, b2, node_embed);

    // edge scores
    k_score<<<(EPOS * 32) / 256, 256>>>(pos_src, pos_dst, out + 1, EPOS, NSRC);
    k_score<<<(ENEG * 32) / 256, 256>>>(neg_src, neg_dst, out + 1 + EPOS, ENEG, NSRC);
}

// round 4
// speedup vs baseline: 5.7119x; 5.7119x over previous
#include <cuda_runtime.h>
#include <cuda_bf16.h>
#include <stdint.h>
#include <math.h>

#define NN    2000
#define NS    1000
#define SP    1024
#define DD    128
#define HH    256
#define BPAIR 100000
#define KNEG  5
#define EPOS  200000
#define ENEG  200000

// ---------------- scratch (static device globals; no allocation) ----------------
__device__ __nv_bfloat16 g_Abf [SP * SP];   // padded A (src x dst), bf16
__device__ __nv_bfloat16 g_Atbf[SP * SP];   // A^T, bf16
__device__ float         g_S1  [SP * SP];   // A @ A^T (fp32 out)
__device__ __nv_bfloat16 g_S1bf[SP * SP];
__device__ float         g_P1  [SP * SP];   // S1 @ A
__device__ float         g_Gp  [SP * SP];   // gamma pre-norm (src block)
__device__ float         g_GpT [SP * SP];   // transpose
__device__ float         g_dsrc[SP];
__device__ float         g_ddst[SP];
__device__ float         g_rn2 [SP];        // row sumsq of Gp
__device__ float         g_cn2 [SP];        // row sumsq of GpT (= col sumsq of Gp)
__device__ float         g_W1t [SP * HH];   // W1 top rows (src), padded
__device__ float         g_W1b [SP * HH];   // W1 bottom rows (dst), padded
__device__ float         g_Tt  [SP * HH];   // Gp  @ W1b
__device__ float         g_Tb  [SP * HH];   // GpT @ W1t
__device__ float         g_T   [NN * HH];   // tanh(..)
__device__ float         g_h   [NN * HH];   // concat(node_embed, sw_h)
__device__ double        g_loss;

__global__ void k_zero_loss() { g_loss = 0.0; }

__device__ __forceinline__ float warp_sum(float v) {
#pragma unroll
    for (int off = 16; off; off >>= 1) v += __shfl_xor_sync(0xffffffffu, v, off);
    return v;
}

// ---------------- pack A block + transpose to bf16 ----------------
__global__ void k_packA(const float* __restrict__ adj) {
    int idx = blockIdx.x * blockDim.x + threadIdx.x;
    if (idx >= SP * SP) return;
    int i = idx >> 10, j = idx & (SP - 1);
    float v = (i < NS && j < NS) ? adj[i * NN + NS + j] : 0.f;
    __nv_bfloat16 b = __float2bfloat16(v);
    g_Abf[i * SP + j]  = b;
    g_Atbf[j * SP + i] = b;
}

__global__ void k_pad_w1s(const float* __restrict__ W1) {
    int idx = blockIdx.x * blockDim.x + threadIdx.x;
    if (idx >= SP * HH) return;
    int i = idx >> 8, c = idx & (HH - 1);
    g_W1t[idx] = (i < NS) ? W1[i * HH + c]        : 0.f;
    g_W1b[idx] = (i < NS) ? W1[(NS + i) * HH + c] : 0.f;
}

// degrees: row sums of bf16 matrix
__global__ void k_deg(const __nv_bfloat16* __restrict__ M, float* __restrict__ d) {
    int row  = blockIdx.x * 8 + (threadIdx.x >> 5);
    int lane = threadIdx.x & 31;
    float s = 0.f;
    for (int j = lane; j < SP; j += 32) s += __bfloat162float(M[row * SP + j]);
    s = warp_sum(s);
    if (lane == 0) d[row] = s;
}

__global__ void k_f2bf(const float* __restrict__ in, __nv_bfloat16* __restrict__ out, int n) {
    int idx = blockIdx.x * blockDim.x + threadIdx.x;
    if (idx < n) out[idx] = __float2bfloat16(in[idx]);
}

// ---------------- bf16 tensor-core GEMM: C(f32) = A @ B, 1024^3, row-major ----------------
__global__ __launch_bounds__(256) void k_bgemm(const __nv_bfloat16* __restrict__ A,
                                               const __nv_bfloat16* __restrict__ B,
                                               float* __restrict__ C) {
    __shared__ __align__(16) __nv_bfloat16 As[128][40];
    __shared__ __align__(16) __nv_bfloat16 Bs[32][136];

    int tid = threadIdx.x, lane = tid & 31, wid = tid >> 5;
    int warp_m = wid >> 2, warp_n = wid & 3;          // 2 x 4 warps -> warp tile 64x32
    int bm = blockIdx.y * 128, bn = blockIdx.x * 128;

    float acc[4][4][4];
#pragma unroll
    for (int i = 0; i < 4; i++)
#pragma unroll
        for (int j = 0; j < 4; j++)
#pragma unroll
            for (int r = 0; r < 4; r++) acc[i][j][r] = 0.f;

    int arow = tid >> 1, acol = (tid & 1) * 16;       // A: 128x32, 16 bf16/thread
    int brow = tid >> 3, bcol = (tid & 7) * 16;       // B: 32x128

    for (int k0 = 0; k0 < SP; k0 += 32) {
        const uint4* ag = (const uint4*)(A + (size_t)(bm + arow) * SP + k0 + acol);
        *(uint4*)&As[arow][acol]     = ag[0];
        *(uint4*)&As[arow][acol + 8] = ag[1];
        const uint4* bg = (const uint4*)(B + (size_t)(k0 + brow) * SP + bn + bcol);
        *(uint4*)&Bs[brow][bcol]     = bg[0];
        *(uint4*)&Bs[brow][bcol + 8] = bg[1];
        __syncthreads();

#pragma unroll
        for (int ks = 0; ks < 2; ks++) {
            uint32_t af[4][4];
#pragma unroll
            for (int mt = 0; mt < 4; mt++) {
                uint32_t addr = (uint32_t)__cvta_generic_to_shared(
                    &As[warp_m * 64 + mt * 16 + (lane & 15)][ks * 16 + ((lane >> 4) << 3)]);
                asm volatile("ldmatrix.sync.aligned.m8n8.x4.shared.b16 {%0,%1,%2,%3}, [%4];"
                             : "=r"(af[mt][0]), "=r"(af[mt][1]), "=r"(af[mt][2]), "=r"(af[mt][3])
                             : "r"(addr));
            }
            uint32_t bfr[2][4];
#pragma unroll
            for (int g = 0; g < 2; g++) {
                uint32_t addr = (uint32_t)__cvta_generic_to_shared(
                    &Bs[ks * 16 + (lane & 15)][warp_n * 32 + g * 16 + ((lane >> 4) << 3)]);
                asm volatile("ldmatrix.sync.aligned.m8n8.x4.trans.shared.b16 {%0,%1,%2,%3}, [%4];"
                             : "=r"(bfr[g][0]), "=r"(bfr[g][1]), "=r"(bfr[g][2]), "=r"(bfr[g][3])
                             : "r"(addr));
            }
#pragma unroll
            for (int mt = 0; mt < 4; mt++)
#pragma unroll
                for (int nt = 0; nt < 4; nt++) {
                    uint32_t b0 = bfr[nt >> 1][(nt & 1) * 2];
                    uint32_t b1 = bfr[nt >> 1][(nt & 1) * 2 + 1];
                    asm volatile(
                        "mma.sync.aligned.m16n8k16.row.col.f32.bf16.bf16.f32 "
                        "{%0,%1,%2,%3}, {%4,%5,%6,%7}, {%8,%9}, {%0,%1,%2,%3};"
                        : "+f"(acc[mt][nt][0]), "+f"(acc[mt][nt][1]),
                          "+f"(acc[mt][nt][2]), "+f"(acc[mt][nt][3])
                        : "r"(af[mt][0]), "r"(af[mt][1]), "r"(af[mt][2]), "r"(af[mt][3]),
                          "r"(b0), "r"(b1));
                }
        }
        __syncthreads();
    }

#pragma unroll
    for (int mt = 0; mt < 4; mt++)
#pragma unroll
        for (int nt = 0; nt < 4; nt++) {
            int row = bm + warp_m * 64 + mt * 16 + (lane >> 2);
            int col = bn + warp_n * 32 + nt * 8 + (lane & 3) * 2;
            *(float2*)&C[(size_t)row * SP + col]       = make_float2(acc[mt][nt][0], acc[mt][nt][1]);
            *(float2*)&C[(size_t)(row + 8) * SP + col] = make_float2(acc[mt][nt][2], acc[mt][nt][3]);
        }
}

// ---------------- gamma pre-norm + row sumsq ----------------
__global__ __launch_bounds__(256) void k_gamma_pre() {
    int r = blockIdx.x, tid = threadIdx.x;
    float dr = g_dsrc[r];
    float sumsq = 0.f;
    for (int j = tid; j < SP; j += 256) {
        float a   = __bfloat162float(g_Abf[r * SP + j]);
        float den = dr * g_ddst[j];
        float g   = (den > 0.f) ? (g_P1[r * SP + j] * a) / den : 0.f;
        g_Gp[r * SP + j] = g;
        sumsq += g * g;
    }
    __shared__ float red[256];
    red[tid] = sumsq;
    __syncthreads();
    for (int s = 128; s > 0; s >>= 1) { if (tid < s) red[tid] += red[tid + s]; __syncthreads(); }
    if (tid == 0) g_rn2[r] = red[0];
}

__global__ void k_transpose(const float* __restrict__ in, float* __restrict__ out) {
    __shared__ float t[32][33];
    int x = blockIdx.x * 32 + threadIdx.x;
    int y = blockIdx.y * 32 + threadIdx.y;
#pragma unroll
    for (int i = 0; i < 4; i++) t[threadIdx.y + 8 * i][threadIdx.x] = in[(size_t)(y + 8 * i) * SP + x];
    __syncthreads();
    x = blockIdx.y * 32 + threadIdx.x;
    y = blockIdx.x * 32 + threadIdx.y;
#pragma unroll
    for (int i = 0; i < 4; i++) out[(size_t)(y + 8 * i) * SP + x] = t[threadIdx.x][threadIdx.y + 8 * i];
}

__global__ __launch_bounds__(256) void k_rowsumsq(const float* __restrict__ M, float* __restrict__ o) {
    int r = blockIdx.x, tid = threadIdx.x;
    float s = 0.f;
    for (int j = tid; j < SP; j += 256) { float v = M[r * SP + j]; s += v * v; }
    __shared__ float red[256];
    red[tid] = s;
    __syncthreads();
    for (int st = 128; st > 0; st >>= 1) { if (tid < st) red[tid] += red[tid + st]; __syncthreads(); }
    if (tid == 0) o[r] = red[0];
}

// ---------------- fp32 SGEMM, batched z=2: Tt = Gp@W1b, Tb = GpT@W1t (M=1024,N=256,K=1024) ----------------
__global__ __launch_bounds__(256) void k_sgemm_w1() {
    const float* A; const float* B; float* C;
    if (blockIdx.z == 0) { A = g_Gp;  B = g_W1b; C = g_Tt; }
    else                 { A = g_GpT; B = g_W1t; C = g_Tb; }

    __shared__ float As[16][68];   // transposed A tile
    __shared__ float Bs[16][68];
    int tid = threadIdx.x;
    int trow = tid >> 4, tcol = tid & 15;
    int bm = blockIdx.y * 64, bn = blockIdx.x * 64;
    int aRow = tid >> 2, aCol = (tid & 3) * 4;
    int bRow = tid >> 4, bCol = (tid & 15) * 4;

    float acc[4][4];
#pragma unroll
    for (int i = 0; i < 4; i++)
#pragma unroll
        for (int j = 0; j < 4; j++) acc[i][j] = 0.f;

    for (int k0 = 0; k0 < SP; k0 += 16) {
        float4 av = *(const float4*)(A + (size_t)(bm + aRow) * SP + k0 + aCol);
        As[aCol + 0][aRow] = av.x; As[aCol + 1][aRow] = av.y;
        As[aCol + 2][aRow] = av.z; As[aCol + 3][aRow] = av.w;
        *(float4*)&Bs[bRow][bCol] = *(const float4*)(B + (size_t)(k0 + bRow) * HH + bn + bCol);
        __syncthreads();
#pragma unroll
        for (int k = 0; k < 16; k++) {
            float4 ra = *(float4*)&As[k][trow * 4];
            float4 rb = *(float4*)&Bs[k][tcol * 4];
            float r_a[4] = {ra.x, ra.y, ra.z, ra.w};
            float r_b[4] = {rb.x, rb.y, rb.z, rb.w};
#pragma unroll
            for (int i = 0; i < 4; i++)
#pragma unroll
                for (int j = 0; j < 4; j++) acc[i][j] += r_a[i] * r_b[j];
        }
        __syncthreads();
    }
#pragma unroll
    for (int i = 0; i < 4; i++) {
        float4 v = make_float4(acc[i][0], acc[i][1], acc[i][2], acc[i][3]);
        *(float4*)(C + (size_t)(bm + trow * 4 + i) * HH + bn + tcol * 4) = v;
    }
}

// ---------------- tanh((T/norm) + b1) into g_T [2000 x 256] ----------------
__global__ void k_tanh_norm(const float* __restrict__ b1) {
    int idx = blockIdx.x * blockDim.x + threadIdx.x;
    if (idx >= NN * HH) return;
    int r = idx >> 8, c = idx & (HH - 1);
    float v;
    if (r < NS) v = g_Tt[r * HH + c] / fmaxf(sqrtf(g_rn2[r]), 1e-12f);
    else { int j = r - NS; v = g_Tb[j * HH + c] / fmaxf(sqrtf(g_cn2[j]), 1e-12f); }
    g_T[idx] = tanhf(v + b1[c]);
}

// ---------------- h[r] = [node_embed[r], T[r] @ W2 + b2] ----------------
__global__ __launch_bounds__(128) void k_fc2_concat(const float* __restrict__ W2,
                                                    const float* __restrict__ b2,
                                                    const float* __restrict__ node_embed) {
    int r = blockIdx.x, j = threadIdx.x;
    __shared__ float tr[HH];
    tr[j]       = g_T[r * HH + j];
    tr[j + 128] = g_T[r * HH + j + 128];
    __syncthreads();
    float s = b2[j];
#pragma unroll 8
    for (int k = 0; k < HH; k++) s += tr[k] * W2[k * DD + j];
    g_h[r * HH + DD + j] = s;
    g_h[r * HH + j]      = node_embed[r * DD + j];
}

// ---------------- skipgram loss ----------------
__global__ __launch_bounds__(256) void k_skipgram(const float* __restrict__ node_embed,
                                                  const float* __restrict__ context_embed,
                                                  const int* __restrict__ pos_u,
                                                  const int* __restrict__ pos_v,
                                                  const int* __restrict__ neg_v) {
    int gwarp = (blockIdx.x * blockDim.x + threadIdx.x) >> 5;
    int lane  = threadIdx.x & 31;
    int wib   = threadIdx.x >> 5;
    float loss = 0.f;
    if (gwarp < BPAIR) {
        int u = pos_u[gwarp];
        int v = pos_v[gwarp];
        float4 eu = ((const float4*)(node_embed    + (size_t)u * DD))[lane];
        float4 ev = ((const float4*)(context_embed + (size_t)v * DD))[lane];
        float pd = eu.x * ev.x + eu.y * ev.y + eu.z * ev.z + eu.w * ev.w;
        pd = warp_sum(pd);
        float pos = fminf(fmaxf(pd, -10.f), 10.f);
        loss = log1pf(expf(-pos));
#pragma unroll
        for (int k = 0; k < KNEG; k++) {
            int nv = neg_v[gwarp * KNEG + k];
            float4 en = ((const float4*)(context_embed + (size_t)nv * DD))[lane];
            float nd = en.x * eu.x + en.y * eu.y + en.z * eu.z + en.w * eu.w;
            nd = warp_sum(nd);
            float neg = fminf(fmaxf(nd, -10.f), 10.f);
            loss += log1pf(expf(neg));
        }
    }
    __shared__ float wl[8];
    if (lane == 0) wl[wib] = loss;
    __syncthreads();
    if (threadIdx.x == 0) {
        float s = 0.f;
#pragma unroll
        for (int w = 0; w < 8; w++) s += wl[w];
        atomicAdd(&g_loss, (double)s);
    }
}

__global__ void k_finalize(float* __restrict__ out) {
    out[0] = (float)(g_loss / (double)BPAIR);
}

// ---------------- edge scores ----------------
__global__ __launch_bounds__(256) void k_score(const int* __restrict__ src,
                                               const int* __restrict__ dst,
                                               float* __restrict__ out, int E, int dstOff) {
    int gwarp = (blockIdx.x * blockDim.x + threadIdx.x) >> 5;
    int lane  = threadIdx.x & 31;
    if (gwarp >= E) return;
    const float4* a = (const float4*)(g_h + (size_t)src[gwarp] * HH);
    const float4* b = (const float4*)(g_h + (size_t)(dstOff + dst[gwarp]) * HH);
    float s = 0.f;
#pragma unroll
    for (int i = 0; i < 2; i++) {
        float4 x = a[lane + 32 * i];
        float4 y = b[lane + 32 * i];
        s += x.x * y.x + x.y * y.y + x.z * y.z + x.w * y.w;
    }
    s = warp_sum(s);
    if (lane == 0) out[gwarp] = s;
}

// ---------------- launch ----------------
extern "C" void kernel_launch(void* const* d_in, const int* in_sizes, int n_in,
                              void* d_out, int out_size) {
    const float* node_embed    = (const float*)d_in[0];
    const float* context_embed = (const float*)d_in[1];
    const float* adj           = (const float*)d_in[2];
    const float* W1            = (const float*)d_in[3];
    const float* b1            = (const float*)d_in[4];
    const float* W2            = (const float*)d_in[5];
    const float* b2            = (const float*)d_in[6];
    const int*   pos_u         = (const int*)d_in[7];
    const int*   pos_v         = (const int*)d_in[8];
    const int*   neg_v         = (const int*)d_in[9];
    const int*   pos_src       = (const int*)d_in[10];
    const int*   pos_dst       = (const int*)d_in[11];
    const int*   neg_src       = (const int*)d_in[12];
    const int*   neg_dst       = (const int*)d_in[13];
    float* out = (float*)d_out;

    __nv_bfloat16 *Abf, *Atbf, *S1bf;
    float *S1, *P1, *Gp, *GpT, *dsrc, *ddst, *cn2;
    cudaGetSymbolAddress((void**)&Abf,  g_Abf);
    cudaGetSymbolAddress((void**)&Atbf, g_Atbf);
    cudaGetSymbolAddress((void**)&S1,   g_S1);
    cudaGetSymbolAddress((void**)&S1bf, g_S1bf);
    cudaGetSymbolAddress((void**)&P1,   g_P1);
    cudaGetSymbolAddress((void**)&Gp,   g_Gp);
    cudaGetSymbolAddress((void**)&GpT,  g_GpT);
    cudaGetSymbolAddress((void**)&dsrc, g_dsrc);
    cudaGetSymbolAddress((void**)&ddst, g_ddst);
    cudaGetSymbolAddress((void**)&cn2,  g_cn2);

    k_zero_loss<<<1, 1>>>();
    // skipgram (independent of graph pipeline)
    k_skipgram<<<(BPAIR * 32) / 256, 256>>>(node_embed, context_embed, pos_u, pos_v, neg_v);
    k_finalize<<<1, 1>>>(out);

    // pack + degrees + W1 split
    k_packA<<<(SP * SP + 255) / 256, 256>>>(adj);
    k_pad_w1s<<<(SP * HH + 255) / 256, 256>>>(W1);
    k_deg<<<SP / 8, 256>>>(Abf,  dsrc);
    k_deg<<<SP / 8, 256>>>(Atbf, ddst);

    // S1 = A @ A^T ; P1 = S1 @ A  (bf16 tensor-core, exact for integer inputs)
    dim3 g88(SP / 128, SP / 128);
    k_bgemm<<<g88, 256>>>(Abf, Atbf, S1);
    k_f2bf<<<(SP * SP + 255) / 256, 256>>>(S1, S1bf, SP * SP);
    k_bgemm<<<g88, 256>>>(S1bf, Abf, P1);

    // gamma pre-norm, transpose, column norms
    k_gamma_pre<<<SP, 256>>>();
    k_transpose<<<dim3(SP / 32, SP / 32), dim3(32, 8)>>>(Gp, GpT);
    k_rowsumsq<<<SP, 256>>>(GpT, cn2);

    // Tt = Gp @ W1b ; Tb = GpT @ W1t  (batched)
    k_sgemm_w1<<<dim3(HH / 64, SP / 64, 2), 256>>>();
    k_tanh_norm<<<(NN * HH + 255) / 256, 256>>>(b1);
    k_fc2_concat<<<NN, 128>>>(W2, b2, node_embed);

    // edge scores
    k_score<<<(EPOS * 32) / 256, 256>>>(pos_src, pos_dst, out + 1, EPOS, NS);
    k_score<<<(ENEG * 32) / 256, 256>>>(neg_src, neg_dst, out + 1 + EPOS, ENEG, NS);
}

// round 5
// speedup vs baseline: 7.7579x; 1.3582x over previous
#include <cuda_runtime.h>
#include <cuda_bf16.h>
#include <stdint.h>
#include <math.h>

#define NN    2000
#define NS    1000
#define SP    1024
#define DD    128
#define HH    256
#define BPAIR 100000
#define KNEG  5
#define EPOS  200000
#define ENEG  200000

// ---------------- scratch (static device globals; no allocation) ----------------
__device__ __nv_bfloat16 g_Abf [SP * SP];   // padded A (src x dst), bf16 (exact 0/1)
__device__ __nv_bfloat16 g_S1bf[SP * SP];   // A @ A^T, bf16 (exact small ints)
__device__ float         g_P1  [SP * SP];   // S1 @ A
__device__ float         g_Gp  [SP * SP];   // gamma pre-norm (src block)
__device__ float         g_dsrc[SP];
__device__ float         g_ddst[SP];
__device__ float         g_T   [NN * HH];   // tanh(norm(gamma)@W1 + b1)
__device__ float         g_h   [NN * HH];   // concat(node_embed, sw_h)
__device__ float         g_part[12500];     // skipgram per-block partial losses

__device__ __forceinline__ float warp_sum(float v) {
#pragma unroll
    for (int off = 16; off; off >>= 1) v += __shfl_xor_sync(0xffffffffu, v, off);
    return v;
}

// ================= front: skipgram ∪ packA ∪ degree sums (block-partitioned) ==========
#define FB_SKIP 12500
#define FB_PACK (FB_SKIP + 4096)
#define FB_DSRC (FB_PACK + 128)
#define FB_DDST (FB_DSRC + 4)

__global__ __launch_bounds__(256) void k_front(const float* __restrict__ adj,
                                               const float* __restrict__ node_embed,
                                               const float* __restrict__ context_embed,
                                               const int* __restrict__ pos_u,
                                               const int* __restrict__ pos_v,
                                               const int* __restrict__ neg_v) {
    int bid = blockIdx.x, tid = threadIdx.x;
    int lane = tid & 31, wib = tid >> 5;

    if (bid < FB_SKIP) {
        // ---- skipgram: 8 warps/block, one pair per warp ----
        int gwarp = bid * 8 + wib;
        int u = pos_u[gwarp];
        int v = pos_v[gwarp];
        float4 eu = ((const float4*)(node_embed    + (size_t)u * DD))[lane];
        float4 ev = ((const float4*)(context_embed + (size_t)v * DD))[lane];
        float pd = eu.x * ev.x + eu.y * ev.y + eu.z * ev.z + eu.w * ev.w;
        pd = warp_sum(pd);
        float pos = fminf(fmaxf(pd, -10.f), 10.f);
        float loss = log1pf(expf(-pos));
#pragma unroll
        for (int k = 0; k < KNEG; k++) {
            int nv = neg_v[gwarp * KNEG + k];
            float4 en = ((const float4*)(context_embed + (size_t)nv * DD))[lane];
            float nd = en.x * eu.x + en.y * eu.y + en.z * eu.z + en.w * eu.w;
            nd = warp_sum(nd);
            float neg = fminf(fmaxf(nd, -10.f), 10.f);
            loss += log1pf(expf(neg));
        }
        __shared__ float wl[8];
        if (lane == 0) wl[wib] = loss;
        __syncthreads();
        if (tid == 0) {
            float s = 0.f;
#pragma unroll
            for (int w = 0; w < 8; w++) s += wl[w];
            g_part[bid] = s;
        }
    } else if (bid < FB_PACK) {
        // ---- pack A block (adj[0:1000, 1000:2000]) into bf16, zero-padded to 1024^2 ----
        int idx = (bid - FB_SKIP) * 256 + tid;
        int i = idx >> 10, j = idx & (SP - 1);
        float v = (i < NS && j < NS) ? adj[i * NN + NS + j] : 0.f;
        g_Abf[idx] = __float2bfloat16(v);
    } else if (bid < FB_DSRC) {
        // ---- dsrc[i] = row sum of A (== diag(A A^T) for binary A) : warp per row ----
        int row = (bid - FB_PACK) * 8 + wib;
        float s = 0.f;
        if (row < NS)
            for (int j = lane; j < NS; j += 32) s += adj[row * NN + NS + j];
        s = warp_sum(s);
        if (lane == 0) g_dsrc[row] = s;
    } else {
        // ---- ddst[j] = col sum of A : thread per column, coalesced over rows ----
        int j = (bid - FB_DSRC) * 256 + tid;
        float s = 0.f;
        if (j < NS)
            for (int i = 0; i < NS; i++) s += adj[i * NN + NS + j];
        g_ddst[j] = s;
    }
}

// finalize loss: deterministic double sum of 12500 partials
__global__ __launch_bounds__(256) void k_finalize(float* __restrict__ out) {
    int tid = threadIdx.x;
    double s = 0.0;
    for (int i = tid; i < 12500; i += 256) s += (double)g_part[i];
    __shared__ double red[256];
    red[tid] = s;
    __syncthreads();
    for (int st = 128; st > 0; st >>= 1) {
        if (tid < st) red[tid] += red[tid + st];
        __syncthreads();
    }
    if (tid == 0) out[0] = (float)(red[0] / (double)BPAIR);
}

// ================= bgemm_nt: S1bf = A @ A^T (both operands g_Abf), 128x64 tiles ==========
__global__ __launch_bounds__(256) void k_bgemm_nt(const __nv_bfloat16* __restrict__ A,
                                                  __nv_bfloat16* __restrict__ C) {
    __shared__ __align__(16) __nv_bfloat16 As[128][40];
    __shared__ __align__(16) __nv_bfloat16 Bs[64][40];

    int tid = threadIdx.x, lane = tid & 31, wid = tid >> 5;
    int warp_m = wid >> 2, warp_n = wid & 3;          // 2 x 4 warps: warp tile 64m x 16n
    int bm = blockIdx.y * 128, bn = blockIdx.x * 64;

    float acc[4][2][4];
#pragma unroll
    for (int i = 0; i < 4; i++)
#pragma unroll
        for (int j = 0; j < 2; j++)
#pragma unroll
            for (int r = 0; r < 4; r++) acc[i][j][r] = 0.f;

    int arow = tid >> 1, acol = (tid & 1) * 16;       // 128x32, 16 bf16/thread
    int brow = tid >> 2, bcol = (tid & 3) * 8;        // 64x32,  8  bf16/thread

    for (int k0 = 0; k0 < SP; k0 += 32) {
        const uint4* ag = (const uint4*)(A + (size_t)(bm + arow) * SP + k0 + acol);
        *(uint4*)&As[arow][acol]     = ag[0];
        *(uint4*)&As[arow][acol + 8] = ag[1];
        *(uint4*)&Bs[brow][bcol] = *(const uint4*)(A + (size_t)(bn + brow) * SP + k0 + bcol);
        __syncthreads();

#pragma unroll
        for (int ks = 0; ks < 2; ks++) {
            uint32_t af[4][4];
#pragma unroll
            for (int mt = 0; mt < 4; mt++) {
                uint32_t addr = (uint32_t)__cvta_generic_to_shared(
                    &As[warp_m * 64 + mt * 16 + (lane & 15)][ks * 16 + ((lane >> 4) << 3)]);
                asm volatile("ldmatrix.sync.aligned.m8n8.x4.shared.b16 {%0,%1,%2,%3}, [%4];"
                             : "=r"(af[mt][0]), "=r"(af[mt][1]), "=r"(af[mt][2]), "=r"(af[mt][3])
                             : "r"(addr));
            }
            uint32_t bf[4];
            {
                uint32_t addr = (uint32_t)__cvta_generic_to_shared(
                    &Bs[warp_n * 16 + (lane & 15)][ks * 16 + ((lane >> 4) << 3)]);
                asm volatile("ldmatrix.sync.aligned.m8n8.x4.shared.b16 {%0,%1,%2,%3}, [%4];"
                             : "=r"(bf[0]), "=r"(bf[1]), "=r"(bf[2]), "=r"(bf[3])
                             : "r"(addr));
            }
#pragma unroll
            for (int mt = 0; mt < 4; mt++)
#pragma unroll
                for (int nt = 0; nt < 2; nt++) {
                    asm volatile(
                        "mma.sync.aligned.m16n8k16.row.col.f32.bf16.bf16.f32 "
                        "{%0,%1,%2,%3}, {%4,%5,%6,%7}, {%8,%9}, {%0,%1,%2,%3};"
                        : "+f"(acc[mt][nt][0]), "+f"(acc[mt][nt][1]),
                          "+f"(acc[mt][nt][2]), "+f"(acc[mt][nt][3])
                        : "r"(af[mt][0]), "r"(af[mt][1]), "r"(af[mt][2]), "r"(af[mt][3]),
                          "r"(bf[nt]), "r"(bf[nt + 2]));
                }
        }
        __syncthreads();
    }

#pragma unroll
    for (int mt = 0; mt < 4; mt++)
#pragma unroll
        for (int nt = 0; nt < 2; nt++) {
            int row = bm + warp_m * 64 + mt * 16 + (lane >> 2);
            int col = bn + warp_n * 16 + nt * 8 + (lane & 3) * 2;
            __nv_bfloat162 lo, hi;
            lo.x = __float2bfloat16(acc[mt][nt][0]); lo.y = __float2bfloat16(acc[mt][nt][1]);
            hi.x = __float2bfloat16(acc[mt][nt][2]); hi.y = __float2bfloat16(acc[mt][nt][3]);
            *(__nv_bfloat162*)&C[(size_t)row * SP + col]       = lo;
            *(__nv_bfloat162*)&C[(size_t)(row + 8) * SP + col] = hi;
        }
}

// ================= bgemm_t: P1 = S1bf @ Abf (B k-major), 128x64 tiles, fp32 out ==========
__global__ __launch_bounds__(256) void k_bgemm_t(const __nv_bfloat16* __restrict__ A,
                                                 const __nv_bfloat16* __restrict__ B,
                                                 float* __restrict__ C) {
    __shared__ __align__(16) __nv_bfloat16 As[128][40];
    __shared__ __align__(16) __nv_bfloat16 Bs[32][72];

    int tid = threadIdx.x, lane = tid & 31, wid = tid >> 5;
    int warp_m = wid >> 2, warp_n = wid & 3;
    int bm = blockIdx.y * 128, bn = blockIdx.x * 64;

    float acc[4][2][4];
#pragma unroll
    for (int i = 0; i < 4; i++)
#pragma unroll
        for (int j = 0; j < 2; j++)
#pragma unroll
            for (int r = 0; r < 4; r++) acc[i][j][r] = 0.f;

    int arow = tid >> 1, acol = (tid & 1) * 16;
    int brow = tid >> 3, bcol = (tid & 7) * 8;        // 32x64, 8 bf16/thread

    for (int k0 = 0; k0 < SP; k0 += 32) {
        const uint4* ag = (const uint4*)(A + (size_t)(bm + arow) * SP + k0 + acol);
        *(uint4*)&As[arow][acol]     = ag[0];
        *(uint4*)&As[arow][acol + 8] = ag[1];
        *(uint4*)&Bs[brow][bcol] = *(const uint4*)(B + (size_t)(k0 + brow) * SP + bn + bcol);
        __syncthreads();

#pragma unroll
        for (int ks = 0; ks < 2; ks++) {
            uint32_t af[4][4];
#pragma unroll
            for (int mt = 0; mt < 4; mt++) {
                uint32_t addr = (uint32_t)__cvta_generic_to_shared(
                    &As[warp_m * 64 + mt * 16 + (lane & 15)][ks * 16 + ((lane >> 4) << 3)]);
                asm volatile("ldmatrix.sync.aligned.m8n8.x4.shared.b16 {%0,%1,%2,%3}, [%4];"
                             : "=r"(af[mt][0]), "=r"(af[mt][1]), "=r"(af[mt][2]), "=r"(af[mt][3])
                             : "r"(addr));
            }
            uint32_t bf[4];
            {
                uint32_t addr = (uint32_t)__cvta_generic_to_shared(
                    &Bs[ks * 16 + (lane & 15)][warp_n * 16 + ((lane >> 4) << 3)]);
                asm volatile("ldmatrix.sync.aligned.m8n8.x4.trans.shared.b16 {%0,%1,%2,%3}, [%4];"
                             : "=r"(bf[0]), "=r"(bf[1]), "=r"(bf[2]), "=r"(bf[3])
                             : "r"(addr));
            }
#pragma unroll
            for (int mt = 0; mt < 4; mt++)
#pragma unroll
                for (int nt = 0; nt < 2; nt++) {
                    asm volatile(
                        "mma.sync.aligned.m16n8k16.row.col.f32.bf16.bf16.f32 "
                        "{%0,%1,%2,%3}, {%4,%5,%6,%7}, {%8,%9}, {%0,%1,%2,%3};"
                        : "+f"(acc[mt][nt][0]), "+f"(acc[mt][nt][1]),
                          "+f"(acc[mt][nt][2]), "+f"(acc[mt][nt][3])
                        : "r"(af[mt][0]), "r"(af[mt][1]), "r"(af[mt][2]), "r"(af[mt][3]),
                          "r"(bf[nt * 2]), "r"(bf[nt * 2 + 1]));
                }
        }
        __syncthreads();
    }

#pragma unroll
    for (int mt = 0; mt < 4; mt++)
#pragma unroll
        for (int nt = 0; nt < 2; nt++) {
            int row = bm + warp_m * 64 + mt * 16 + (lane >> 2);
            int col = bn + warp_n * 16 + nt * 8 + (lane & 3) * 2;
            *(float2*)&C[(size_t)row * SP + col]       = make_float2(acc[mt][nt][0], acc[mt][nt][1]);
            *(float2*)&C[(size_t)(row + 8) * SP + col] = make_float2(acc[mt][nt][2], acc[mt][nt][3]);
        }
}

// ================= gamma (elementwise): Gp = where(d_i*d_j>0, P1*A/(d_i*d_j), 0) ==========
__global__ __launch_bounds__(256) void k_gamma() {
    int idx = blockIdx.x * 256 + threadIdx.x;
    int r = idx >> 10, j = idx & (SP - 1);
    float a   = __bfloat162float(g_Abf[idx]);
    float den = g_dsrc[r] * g_ddst[j];
    g_Gp[idx] = (den > 0.f) ? (g_P1[idx] * a) / den : 0.f;
}

// ================= sparse gamma@W1 + norm + bias + tanh ==========
// CTA b < 1000 : src row r=b   : T[b]    = tanh( (Gp[r,:]/||Gp[r,:]||) @ W1[1000+..] + b1 )
// CTA b >= 1000: dst col c=b-NS: T[b]    = tanh( (Gp[:,c]/||Gp[:,c]||) @ W1[..]      + b1 )
__global__ __launch_bounds__(256) void k_spmm_w1(const float* __restrict__ W1,
                                                 const float* __restrict__ b1) {
    __shared__ int   sidx[SP];
    __shared__ float sval[SP];
    __shared__ float sred[256];
    __shared__ int   sscan[256];
    __shared__ float s_inv;
    __shared__ int   s_total;

    int b = blockIdx.x, t = threadIdx.x;
    bool rowmode = (b < NS);

    // phase 1: load 4 elements/thread, sumsq + deterministic compaction
    float v[4];
    int   ji[4];
    if (rowmode) {
        float4 q = *(const float4*)&g_Gp[(size_t)b * SP + t * 4];
        v[0] = q.x; v[1] = q.y; v[2] = q.z; v[3] = q.w;
#pragma unroll
        for (int i = 0; i < 4; i++) ji[i] = t * 4 + i;
    } else {
        int c = b - NS;
#pragma unroll
        for (int i = 0; i < 4; i++) {
            int r = t * 4 + i;
            v[i]  = g_Gp[(size_t)r * SP + c];
            ji[i] = r;
        }
    }
    float ss = v[0] * v[0] + v[1] * v[1] + v[2] * v[2] + v[3] * v[3];
    sred[t] = ss;
    int cnt = (v[0] != 0.f) + (v[1] != 0.f) + (v[2] != 0.f) + (v[3] != 0.f);
    sscan[t] = cnt;
    __syncthreads();
    // sumsq tree + inclusive scan (Hillis-Steele)
    for (int st = 128; st > 0; st >>= 1) {
        if (t < st) sred[t] += sred[t + st];
        __syncthreads();
    }
    for (int off = 1; off < 256; off <<= 1) {
        int x = (t >= off) ? sscan[t - off] : 0;
        __syncthreads();
        sscan[t] += x;
        __syncthreads();
    }
    if (t == 0) {
        s_inv   = 1.f / fmaxf(sqrtf(sred[0]), 1e-12f);
        s_total = sscan[255];
    }
    int pos = sscan[t] - cnt;
    __syncthreads();
#pragma unroll
    for (int i = 0; i < 4; i++) {
        if (v[i] != 0.f) {
            sidx[pos] = ji[i];
            sval[pos] = v[i];
            pos++;
        }
    }
    __syncthreads();

    // phase 2: accumulate gathered W1 rows (t = output column, coalesced)
    int total = s_total;
    int w1off = rowmode ? NS : 0;   // row mode uses W1 bottom rows, col mode top rows
    float acc = 0.f;
    for (int p = 0; p < total; p++) {
        int   j = sidx[p];
        float g = sval[p];
        acc += g * W1[(size_t)(w1off + j) * HH + t];
    }
    g_T[(size_t)b * HH + t] = tanhf(acc * s_inv + b1[t]);
}

// ================= h[r] = [node_embed[r], T[r] @ W2 + b2] ==========
__global__ __launch_bounds__(128) void k_fc2_concat(const float* __restrict__ W2,
                                                    const float* __restrict__ b2,
                                                    const float* __restrict__ node_embed) {
    int r = blockIdx.x, j = threadIdx.x;
    __shared__ float tr[HH];
    tr[j]       = g_T[r * HH + j];
    tr[j + 128] = g_T[r * HH + j + 128];
    __syncthreads();
    float s = b2[j];
#pragma unroll 8
    for (int k = 0; k < HH; k++) s += tr[k] * W2[k * DD + j];
    g_h[r * HH + DD + j] = s;
    g_h[r * HH + j]      = node_embed[r * DD + j];
}

// ================= fused edge scores (pos + neg in one launch) ==========
__global__ __launch_bounds__(256) void k_score_all(const int* __restrict__ pos_src,
                                                   const int* __restrict__ pos_dst,
                                                   const int* __restrict__ neg_src,
                                                   const int* __restrict__ neg_dst,
                                                   float* __restrict__ out) {
    int gwarp = (blockIdx.x * blockDim.x + threadIdx.x) >> 5;
    int lane  = threadIdx.x & 31;
    int s_idx, d_idx;
    float* o;
    if (gwarp < EPOS) {
        s_idx = pos_src[gwarp];
        d_idx = pos_dst[gwarp];
        o = out + 1 + gwarp;
    } else {
        int e = gwarp - EPOS;
        s_idx = neg_src[e];
        d_idx = neg_dst[e];
        o = out + 1 + EPOS + e;
    }
    const float4* a = (const float4*)(g_h + (size_t)s_idx * HH);
    const float4* bb = (const float4*)(g_h + (size_t)(NS + d_idx) * HH);
    float s = 0.f;
#pragma unroll
    for (int i = 0; i < 2; i++) {
        float4 x = a[lane + 32 * i];
        float4 y = bb[lane + 32 * i];
        s += x.x * y.x + x.y * y.y + x.z * y.z + x.w * y.w;
    }
    s = warp_sum(s);
    if (lane == 0) *o = s;
}

// ---------------- launch ----------------
extern "C" void kernel_launch(void* const* d_in, const int* in_sizes, int n_in,
                              void* d_out, int out_size) {
    const float* node_embed    = (const float*)d_in[0];
    const float* context_embed = (const float*)d_in[1];
    const float* adj           = (const float*)d_in[2];
    const float* W1            = (const float*)d_in[3];
    const float* b1            = (const float*)d_in[4];
    const float* W2            = (const float*)d_in[5];
    const float* b2            = (const float*)d_in[6];
    const int*   pos_u         = (const int*)d_in[7];
    const int*   pos_v         = (const int*)d_in[8];
    const int*   neg_v         = (const int*)d_in[9];
    const int*   pos_src       = (const int*)d_in[10];
    const int*   pos_dst       = (const int*)d_in[11];
    const int*   neg_src       = (const int*)d_in[12];
    const int*   neg_dst       = (const int*)d_in[13];
    float* out = (float*)d_out;

    __nv_bfloat16 *Abf, *S1bf;
    float *P1;
    cudaGetSymbolAddress((void**)&Abf,  g_Abf);
    cudaGetSymbolAddress((void**)&S1bf, g_S1bf);
    cudaGetSymbolAddress((void**)&P1,   g_P1);

    // front: skipgram + pack + degrees (one big fused launch)
    k_front<<<FB_DDST, 256>>>(adj, node_embed, context_embed, pos_u, pos_v, neg_v);
    k_finalize<<<1, 256>>>(out);

    // S1 = A @ A^T (bf16 epilogue) ; P1 = S1 @ A
    dim3 g(SP / 64, SP / 128);
    k_bgemm_nt<<<g, 256>>>(Abf, S1bf);
    k_bgemm_t<<<g, 256>>>(S1bf, Abf, P1);

    // gamma, sparse @W1 (+norm+tanh), fc2+concat
    k_gamma<<<SP * SP / 256, 256>>>();
    k_spmm_w1<<<NN, 256>>>(W1, b1);
    k_fc2_concat<<<NN, 128>>>(W2, b2, node_embed);

    // fused edge scores
    k_score_all<<<(EPOS + ENEG) / 8, 256>>>(pos_src, pos_dst, neg_src, neg_dst, out);
}

// round 6
// speedup vs baseline: 10.8215x; 1.3949x over previous
#include <cuda_runtime.h>
#include <cuda_bf16.h>
#include <stdint.h>
#include <math.h>

#define NN    2000
#define NS    1000
#define SP    1024
#define DD    128
#define HH    256
#define BPAIR 100000
#define KNEG  5
#define EPOS  200000
#define ENEG  200000

#define NPD   2048        // padded node count (skipgram matrix dim)
#define KS3   384         // 3*128 split-K for skipgram
#define KH3   768         // 3*256 split-K for edge scores
#define NSKB  391         // ceil(100000/256)

// ---------------- scratch (static device globals; no allocation) ----------------
__device__ __nv_bfloat16 g_Abf [SP * SP];     // padded A (src x dst), bf16 exact 0/1
__device__ __nv_bfloat16 g_S1bf[SP * SP];     // A @ A^T, bf16 exact small ints
__device__ float         g_Gp  [SP * SP];     // gamma pre-norm (src block)
__device__ float         g_dsrc[SP];
__device__ float         g_ddst[SP];
__device__ float         g_T   [NN * HH];     // tanh(norm(gamma)@W1 + b1)
__device__ __nv_bfloat16 g_Na  [NPD * KS3];   // node_embed split, A-form [hi,hi,lo]
__device__ __nv_bfloat16 g_Cb  [NPD * KS3];   // context_embed split, B-form [hi,lo,hi]
__device__ float         g_M   [NPD * NPD];   // node @ context^T (all-pairs)
__device__ __nv_bfloat16 g_Hs  [SP * KH3];    // h_src split, A-form
__device__ __nv_bfloat16 g_Hd  [SP * KH3];    // h_dst split, B-form
__device__ float         g_S   [SP * SP];     // h_src @ h_dst^T
__device__ float         g_part[NSKB];

__device__ __forceinline__ float warp_sum(float v) {
#pragma unroll
    for (int off = 16; off; off >>= 1) v += __shfl_xor_sync(0xffffffffu, v, off);
    return v;
}

__device__ __forceinline__ uint32_t sA(const void* p) {
    return (uint32_t)__cvta_generic_to_shared(p);
}
__device__ __forceinline__ void cp16(uint32_t dst, const void* src) {
    asm volatile("cp.async.cg.shared.global [%0], [%1], 16;" :: "r"(dst), "l"(src) : "memory");
}
__device__ __forceinline__ void cp_commit() {
    asm volatile("cp.async.commit_group;" ::: "memory");
}
__device__ __forceinline__ void cp_wait1() {
    asm volatile("cp.async.wait_group 1;" ::: "memory");
}
__device__ __forceinline__ void cp_wait0() {
    asm volatile("cp.async.wait_group 0;" ::: "memory");
}
__device__ __forceinline__ void split_bf(float x, __nv_bfloat16& hi, __nv_bfloat16& lo) {
    hi = __float2bfloat16(x);
    lo = __float2bfloat16(x - __bfloat162float(hi));
}

// ================= front: packA ∪ degrees ∪ split-pack embeds ==========
#define FB_PACK 4096
#define FB_DSRC (FB_PACK + 128)
#define FB_DDST (FB_DSRC + 4)
#define FB_SKPK (FB_DDST + 1024)

__global__ __launch_bounds__(256) void k_front(const float* __restrict__ adj,
                                               const float* __restrict__ node_embed,
                                               const float* __restrict__ context_embed) {
    int bid = blockIdx.x, tid = threadIdx.x;
    int lane = tid & 31, wib = tid >> 5;

    if (bid < FB_PACK) {
        int idx = bid * 256 + tid;
        int i = idx >> 10, j = idx & (SP - 1);
        float v = (i < NS && j < NS) ? adj[i * NN + NS + j] : 0.f;
        g_Abf[idx] = __float2bfloat16(v);
    } else if (bid < FB_DSRC) {
        int row = (bid - FB_PACK) * 8 + wib;
        float s = 0.f;
        if (row < NS)
            for (int j = lane; j < NS; j += 32) s += adj[row * NN + NS + j];
        s = warp_sum(s);
        if (lane == 0) g_dsrc[row] = (row < NS) ? s : 0.f;
    } else if (bid < FB_DDST) {
        int j = (bid - FB_DSRC) * 256 + tid;
        float s = 0.f;
        if (j < NS)
            for (int i = 0; i < NS; i++) s += adj[i * NN + NS + j];
        g_ddst[j] = s;
    } else {
        // split-pack node/context embeds: idx over 2048 x 128
        int idx = (bid - FB_DDST) * 256 + tid;
        int r = idx >> 7, c = idx & 127;
        float xn = (r < NN) ? node_embed[r * DD + c] : 0.f;
        float xc = (r < NN) ? context_embed[r * DD + c] : 0.f;
        __nv_bfloat16 nh, nl, ch, cl;
        split_bf(xn, nh, nl);
        split_bf(xc, ch, cl);
        size_t base = (size_t)r * KS3 + c;
        g_Na[base]       = nh;  g_Na[base + 128] = nh;  g_Na[base + 256] = nl;
        g_Cb[base]       = ch;  g_Cb[base + 128] = cl;  g_Cb[base + 256] = ch;
    }
}

// ================= generic NT GEMM: C[M,N] = A[M,K] @ B[N,K]^T, bf16 in, 128x64 tiles ====
// 2-stage cp.async pipeline. OUT_BF16 selects bf16 or fp32 output.
template<int KDIM, bool OUT_BF16>
__global__ __launch_bounds__(256) void k_gemm_nt(const __nv_bfloat16* __restrict__ A,
                                                 const __nv_bfloat16* __restrict__ B,
                                                 float* __restrict__ Cf,
                                                 __nv_bfloat16* __restrict__ Cbf,
                                                 int ldc) {
    __shared__ __align__(16) __nv_bfloat16 As[2][128][40];
    __shared__ __align__(16) __nv_bfloat16 Bs[2][64][40];
    constexpr int NIT = KDIM / 32;

    int tid = threadIdx.x, lane = tid & 31, wid = tid >> 5;
    int warp_m = wid >> 2, warp_n = wid & 3;
    int bm = blockIdx.y * 128, bn = blockIdx.x * 64;

    float acc[4][2][4];
#pragma unroll
    for (int i = 0; i < 4; i++)
#pragma unroll
        for (int j = 0; j < 2; j++)
#pragma unroll
            for (int r = 0; r < 4; r++) acc[i][j][r] = 0.f;

    int arow = tid >> 1, acol = (tid & 1) * 16;
    int brow = tid >> 2, bcol = (tid & 3) * 8;

    auto issue = [&](int it, int buf) {
        const __nv_bfloat16* ag = A + (size_t)(bm + arow) * KDIM + it * 32 + acol;
        cp16(sA(&As[buf][arow][acol]), ag);
        cp16(sA(&As[buf][arow][acol + 8]), ag + 8);
        cp16(sA(&Bs[buf][brow][bcol]), B + (size_t)(bn + brow) * KDIM + it * 32 + bcol);
        cp_commit();
    };

    issue(0, 0);
    issue(1, 1);

    for (int it = 0; it < NIT; it++) {
        int buf = it & 1;
        if (it < NIT - 1) cp_wait1(); else cp_wait0();
        __syncthreads();
#pragma unroll
        for (int ks = 0; ks < 2; ks++) {
            uint32_t af[4][4];
#pragma unroll
            for (int mt = 0; mt < 4; mt++) {
                uint32_t addr = sA(&As[buf][warp_m * 64 + mt * 16 + (lane & 15)][ks * 16 + ((lane >> 4) << 3)]);
                asm volatile("ldmatrix.sync.aligned.m8n8.x4.shared.b16 {%0,%1,%2,%3}, [%4];"
                             : "=r"(af[mt][0]), "=r"(af[mt][1]), "=r"(af[mt][2]), "=r"(af[mt][3])
                             : "r"(addr));
            }
            uint32_t bf[4];
            {
                uint32_t addr = sA(&Bs[buf][warp_n * 16 + (lane & 15)][ks * 16 + ((lane >> 4) << 3)]);
                asm volatile("ldmatrix.sync.aligned.m8n8.x4.shared.b16 {%0,%1,%2,%3}, [%4];"
                             : "=r"(bf[0]), "=r"(bf[1]), "=r"(bf[2]), "=r"(bf[3])
                             : "r"(addr));
            }
#pragma unroll
            for (int mt = 0; mt < 4; mt++)
#pragma unroll
                for (int nt = 0; nt < 2; nt++) {
                    asm volatile(
                        "mma.sync.aligned.m16n8k16.row.col.f32.bf16.bf16.f32 "
                        "{%0,%1,%2,%3}, {%4,%5,%6,%7}, {%8,%9}, {%0,%1,%2,%3};"
                        : "+f"(acc[mt][nt][0]), "+f"(acc[mt][nt][1]),
                          "+f"(acc[mt][nt][2]), "+f"(acc[mt][nt][3])
                        : "r"(af[mt][0]), "r"(af[mt][1]), "r"(af[mt][2]), "r"(af[mt][3]),
                          "r"(bf[nt]), "r"(bf[nt + 2]));
                }
        }
        __syncthreads();
        if (it + 2 < NIT) issue(it + 2, buf);
    }

#pragma unroll
    for (int mt = 0; mt < 4; mt++)
#pragma unroll
        for (int nt = 0; nt < 2; nt++) {
            int row = bm + warp_m * 64 + mt * 16 + (lane >> 2);
            int col = bn + warp_n * 16 + nt * 8 + (lane & 3) * 2;
            if (OUT_BF16) {
                __nv_bfloat162 lo, hi;
                lo.x = __float2bfloat16(acc[mt][nt][0]); lo.y = __float2bfloat16(acc[mt][nt][1]);
                hi.x = __float2bfloat16(acc[mt][nt][2]); hi.y = __float2bfloat16(acc[mt][nt][3]);
                *(__nv_bfloat162*)&Cbf[(size_t)row * ldc + col]       = lo;
                *(__nv_bfloat162*)&Cbf[(size_t)(row + 8) * ldc + col] = hi;
            } else {
                *(float2*)&Cf[(size_t)row * ldc + col]       = make_float2(acc[mt][nt][0], acc[mt][nt][1]);
                *(float2*)&Cf[(size_t)(row + 8) * ldc + col] = make_float2(acc[mt][nt][2], acc[mt][nt][3]);
            }
        }
}

// ================= P1 GEMM (B k-major) with fused gamma epilogue ==========
// Gp[i,j] = (dsrc[i]*ddst[j] > 0) ? (S1@A)[i,j] * A[i,j] / (dsrc[i]*ddst[j]) : 0
__global__ __launch_bounds__(256) void k_gemm_tg(const __nv_bfloat16* __restrict__ A,
                                                 const __nv_bfloat16* __restrict__ B) {
    __shared__ __align__(16) __nv_bfloat16 As[2][128][40];
    __shared__ __align__(16) __nv_bfloat16 Bs[2][32][72];
    const int NIT = SP / 32;

    int tid = threadIdx.x, lane = tid & 31, wid = tid >> 5;
    int warp_m = wid >> 2, warp_n = wid & 3;
    int bm = blockIdx.y * 128, bn = blockIdx.x * 64;

    float acc[4][2][4];
#pragma unroll
    for (int i = 0; i < 4; i++)
#pragma unroll
        for (int j = 0; j < 2; j++)
#pragma unroll
            for (int r = 0; r < 4; r++) acc[i][j][r] = 0.f;

    int arow = tid >> 1, acol = (tid & 1) * 16;
    int brow = tid >> 3, bcol = (tid & 7) * 8;

    auto issue = [&](int it, int buf) {
        const __nv_bfloat16* ag = A + (size_t)(bm + arow) * SP + it * 32 + acol;
        cp16(sA(&As[buf][arow][acol]), ag);
        cp16(sA(&As[buf][arow][acol + 8]), ag + 8);
        cp16(sA(&Bs[buf][brow][bcol]), B + (size_t)(it * 32 + brow) * SP + bn + bcol);
        cp_commit();
    };

    issue(0, 0);
    issue(1, 1);

    for (int it = 0; it < NIT; it++) {
        int buf = it & 1;
        if (it < NIT - 1) cp_wait1(); else cp_wait0();
        __syncthreads();
#pragma unroll
        for (int ks = 0; ks < 2; ks++) {
            uint32_t af[4][4];
#pragma unroll
            for (int mt = 0; mt < 4; mt++) {
                uint32_t addr = sA(&As[buf][warp_m * 64 + mt * 16 + (lane & 15)][ks * 16 + ((lane >> 4) << 3)]);
                asm volatile("ldmatrix.sync.aligned.m8n8.x4.shared.b16 {%0,%1,%2,%3}, [%4];"
                             : "=r"(af[mt][0]), "=r"(af[mt][1]), "=r"(af[mt][2]), "=r"(af[mt][3])
                             : "r"(addr));
            }
            uint32_t bf[4];
            {
                uint32_t addr = sA(&Bs[buf][ks * 16 + (lane & 15)][warp_n * 16 + ((lane >> 4) << 3)]);
                asm volatile("ldmatrix.sync.aligned.m8n8.x4.trans.shared.b16 {%0,%1,%2,%3}, [%4];"
                             : "=r"(bf[0]), "=r"(bf[1]), "=r"(bf[2]), "=r"(bf[3])
                             : "r"(addr));
            }
#pragma unroll
            for (int mt = 0; mt < 4; mt++)
#pragma unroll
                for (int nt = 0; nt < 2; nt++) {
                    asm volatile(
                        "mma.sync.aligned.m16n8k16.row.col.f32.bf16.bf16.f32 "
                        "{%0,%1,%2,%3}, {%4,%5,%6,%7}, {%8,%9}, {%0,%1,%2,%3};"
                        : "+f"(acc[mt][nt][0]), "+f"(acc[mt][nt][1]),
                          "+f"(acc[mt][nt][2]), "+f"(acc[mt][nt][3])
                        : "r"(af[mt][0]), "r"(af[mt][1]), "r"(af[mt][2]), "r"(af[mt][3]),
                          "r"(bf[nt * 2]), "r"(bf[nt * 2 + 1]));
                }
        }
        __syncthreads();
        if (it + 2 < NIT) issue(it + 2, buf);
    }

    // fused gamma epilogue
#pragma unroll
    for (int mt = 0; mt < 4; mt++) {
        int row = bm + warp_m * 64 + mt * 16 + (lane >> 2);
        float dr0 = g_dsrc[row], dr1 = g_dsrc[row + 8];
#pragma unroll
        for (int nt = 0; nt < 2; nt++) {
            int col = bn + warp_n * 16 + nt * 8 + (lane & 3) * 2;
            float dc0 = g_ddst[col], dc1 = g_ddst[col + 1];
            __nv_bfloat162 a0 = *(const __nv_bfloat162*)&g_Abf[(size_t)row * SP + col];
            __nv_bfloat162 a1 = *(const __nv_bfloat162*)&g_Abf[(size_t)(row + 8) * SP + col];
            float d00 = dr0 * dc0, d01 = dr0 * dc1, d10 = dr1 * dc0, d11 = dr1 * dc1;
            float g00 = (d00 > 0.f) ? acc[mt][nt][0] * __bfloat162float(a0.x) / d00 : 0.f;
            float g01 = (d01 > 0.f) ? acc[mt][nt][1] * __bfloat162float(a0.y) / d01 : 0.f;
            float g10 = (d10 > 0.f) ? acc[mt][nt][2] * __bfloat162float(a1.x) / d10 : 0.f;
            float g11 = (d11 > 0.f) ? acc[mt][nt][3] * __bfloat162float(a1.y) / d11 : 0.f;
            *(float2*)&g_Gp[(size_t)row * SP + col]       = make_float2(g00, g01);
            *(float2*)&g_Gp[(size_t)(row + 8) * SP + col] = make_float2(g10, g11);
        }
    }
}

// ================= skipgram gather from all-pairs matrix ==========
__global__ __launch_bounds__(256) void k_skip_gather(const int* __restrict__ pos_u,
                                                     const int* __restrict__ pos_v,
                                                     const int* __restrict__ neg_v) {
    int t = blockIdx.x * 256 + threadIdx.x;
    float loss = 0.f;
    if (t < BPAIR) {
        int u = pos_u[t];
        const float* Mu = g_M + (size_t)u * NPD;
        float pos = fminf(fmaxf(Mu[pos_v[t]], -10.f), 10.f);
        loss = log1pf(expf(-pos));
#pragma unroll
        for (int k = 0; k < KNEG; k++) {
            float neg = fminf(fmaxf(Mu[neg_v[t * KNEG + k]], -10.f), 10.f);
            loss += log1pf(expf(neg));
        }
    }
    __shared__ float red[256];
    red[threadIdx.x] = loss;
    __syncthreads();
    for (int s = 128; s > 0; s >>= 1) {
        if (threadIdx.x < s) red[threadIdx.x] += red[threadIdx.x + s];
        __syncthreads();
    }
    if (threadIdx.x == 0) g_part[blockIdx.x] = red[0];
}

__global__ __launch_bounds__(256) void k_finalize(float* __restrict__ out) {
    int tid = threadIdx.x;
    double s = 0.0;
    for (int i = tid; i < NSKB; i += 256) s += (double)g_part[i];
    __shared__ double red[256];
    red[tid] = s;
    __syncthreads();
    for (int st = 128; st > 0; st >>= 1) {
        if (tid < st) red[tid] += red[tid + st];
        __syncthreads();
    }
    if (tid == 0) out[0] = (float)(red[0] / (double)BPAIR);
}

// ================= sparse gamma@W1 + norm + bias + tanh (unchanged, passing) ==========
__global__ __launch_bounds__(256) void k_spmm_w1(const float* __restrict__ W1,
                                                 const float* __restrict__ b1) {
    __shared__ int   sidx[SP];
    __shared__ float sval[SP];
    __shared__ float sred[256];
    __shared__ int   sscan[256];
    __shared__ float s_inv;
    __shared__ int   s_total;

    int b = blockIdx.x, t = threadIdx.x;
    bool rowmode = (b < NS);

    float v[4];
    int   ji[4];
    if (rowmode) {
        float4 q = *(const float4*)&g_Gp[(size_t)b * SP + t * 4];
        v[0] = q.x; v[1] = q.y; v[2] = q.z; v[3] = q.w;
#pragma unroll
        for (int i = 0; i < 4; i++) ji[i] = t * 4 + i;
    } else {
        int c = b - NS;
#pragma unroll
        for (int i = 0; i < 4; i++) {
            int r = t * 4 + i;
            v[i]  = g_Gp[(size_t)r * SP + c];
            ji[i] = r;
        }
    }
    float ss = v[0] * v[0] + v[1] * v[1] + v[2] * v[2] + v[3] * v[3];
    sred[t] = ss;
    int cnt = (v[0] != 0.f) + (v[1] != 0.f) + (v[2] != 0.f) + (v[3] != 0.f);
    sscan[t] = cnt;
    __syncthreads();
    for (int st = 128; st > 0; st >>= 1) {
        if (t < st) sred[t] += sred[t + st];
        __syncthreads();
    }
    for (int off = 1; off < 256; off <<= 1) {
        int x = (t >= off) ? sscan[t - off] : 0;
        __syncthreads();
        sscan[t] += x;
        __syncthreads();
    }
    if (t == 0) {
        s_inv   = 1.f / fmaxf(sqrtf(sred[0]), 1e-12f);
        s_total = sscan[255];
    }
    int pos = sscan[t] - cnt;
    __syncthreads();
#pragma unroll
    for (int i = 0; i < 4; i++) {
        if (v[i] != 0.f) {
            sidx[pos] = ji[i];
            sval[pos] = v[i];
            pos++;
        }
    }
    __syncthreads();

    int total = s_total;
    int w1off = rowmode ? NS : 0;
    float acc = 0.f;
    for (int p = 0; p < total; p++) {
        acc += sval[p] * W1[(size_t)(w1off + sidx[p]) * HH + t];
    }
    g_T[(size_t)b * HH + t] = tanhf(acc * s_inv + b1[t]);
}

// ================= fc2 + concat + split-bf16 pack of h rows ==========
__global__ __launch_bounds__(128) void k_fc2_concat(const float* __restrict__ W2,
                                                    const float* __restrict__ b2,
                                                    const float* __restrict__ node_embed) {
    int b = blockIdx.x, j = threadIdx.x;
    if (b >= NN) {
        // zero pad rows 1000..1023 of Hs / Hd
        int idx = b - NN;                // 0..47
        __nv_bfloat16* dst = (idx < 24) ? g_Hs : g_Hd;
        int row = NS + (idx % 24);
#pragma unroll
        for (int q = 0; q < 6; q++) dst[(size_t)row * KH3 + q * 128 + j] = __float2bfloat16(0.f);
        return;
    }
    int r = b;
    __shared__ float tr[HH];
    tr[j]       = g_T[r * HH + j];
    tr[j + 128] = g_T[r * HH + j + 128];
    __syncthreads();
    float s = b2[j];
#pragma unroll 8
    for (int k = 0; k < HH; k++) s += tr[k] * W2[k * DD + j];
    float a = node_embed[r * DD + j];

    bool srcside = (r < NS);
    __nv_bfloat16* dst = srcside ? g_Hs : g_Hd;
    size_t rowb = (size_t)(srcside ? r : r - NS) * KH3;
    __nv_bfloat16 ah, al, sh, sl;
    split_bf(a, ah, al);
    split_bf(s, sh, sl);
    if (srcside) {
        // A-form: [hi, hi, lo] blocks of 256
        dst[rowb + j]             = ah;  dst[rowb + 128 + j]       = sh;
        dst[rowb + 256 + j]       = ah;  dst[rowb + 384 + j]       = sh;
        dst[rowb + 512 + j]       = al;  dst[rowb + 640 + j]       = sl;
    } else {
        // B-form: [hi, lo, hi]
        dst[rowb + j]             = ah;  dst[rowb + 128 + j]       = sh;
        dst[rowb + 256 + j]       = al;  dst[rowb + 384 + j]       = sl;
        dst[rowb + 512 + j]       = ah;  dst[rowb + 640 + j]       = sh;
    }
}

// ================= edge score gather ==========
__global__ __launch_bounds__(256) void k_score_gather(const int* __restrict__ pos_src,
                                                      const int* __restrict__ pos_dst,
                                                      const int* __restrict__ neg_src,
                                                      const int* __restrict__ neg_dst,
                                                      float* __restrict__ out) {
    int t = blockIdx.x * 256 + threadIdx.x;
    if (t < EPOS) {
        out[1 + t] = g_S[(size_t)pos_src[t] * SP + pos_dst[t]];
    } else if (t < EPOS + ENEG) {
        int e = t - EPOS;
        out[1 + EPOS + e] = g_S[(size_t)neg_src[e] * SP + neg_dst[e]];
    }
}

// ---------------- launch ----------------
extern "C" void kernel_launch(void* const* d_in, const int* in_sizes, int n_in,
                              void* d_out, int out_size) {
    const float* node_embed    = (const float*)d_in[0];
    const float* context_embed = (const float*)d_in[1];
    const float* adj           = (const float*)d_in[2];
    const float* W1            = (const float*)d_in[3];
    const float* b1            = (const float*)d_in[4];
    const float* W2            = (const float*)d_in[5];
    const float* b2            = (const float*)d_in[6];
    const int*   pos_u         = (const int*)d_in[7];
    const int*   pos_v         = (const int*)d_in[8];
    const int*   neg_v         = (const int*)d_in[9];
    const int*   pos_src       = (const int*)d_in[10];
    const int*   pos_dst       = (const int*)d_in[11];
    const int*   neg_src       = (const int*)d_in[12];
    const int*   neg_dst       = (const int*)d_in[13];
    float* out = (float*)d_out;

    __nv_bfloat16 *Abf, *S1bf, *Na, *Cb, *Hs, *Hd;
    float *M, *S;
    cudaGetSymbolAddress((void**)&Abf,  g_Abf);
    cudaGetSymbolAddress((void**)&S1bf, g_S1bf);
    cudaGetSymbolAddress((void**)&Na,   g_Na);
    cudaGetSymbolAddress((void**)&Cb,   g_Cb);
    cudaGetSymbolAddress((void**)&Hs,   g_Hs);
    cudaGetSymbolAddress((void**)&Hd,   g_Hd);
    cudaGetSymbolAddress((void**)&M,    g_M);
    cudaGetSymbolAddress((void**)&S,    g_S);

    // front: pack A, degrees, split-pack embeds
    k_front<<<FB_SKPK, 256>>>(adj, node_embed, context_embed);

    // skipgram all-pairs matrix + gather + finalize
    k_gemm_nt<KS3, false><<<dim3(NPD / 64, NPD / 128), 256>>>(Na, Cb, M, nullptr, NPD);
    k_skip_gather<<<NSKB, 256>>>(pos_u, pos_v, neg_v);
    k_finalize<<<1, 256>>>(out);

    // S1 = A @ A^T (bf16 out) ; Gp = gamma(S1 @ A) fused
    k_gemm_nt<SP, true><<<dim3(SP / 64, SP / 128), 256>>>(Abf, Abf, nullptr, S1bf, SP);
    k_gemm_tg<<<dim3(SP / 64, SP / 128), 256>>>(S1bf, Abf);

    // sparse gamma@W1 (+norm+tanh), fc2 + concat + split pack
    k_spmm_w1<<<NN, 256>>>(W1, b1);
    k_fc2_concat<<<NN + 48, 128>>>(W2, b2, node_embed);

    // edge score matrix + gather
    k_gemm_nt<KH3, false><<<dim3(SP / 64, SP / 128), 256>>>(Hs, Hd, S, nullptr, SP);
    k_score_gather<<<(EPOS + ENEG + 255) / 256, 256>>>(pos_src, pos_dst, neg_src, neg_dst, out);
}